// round 12
// baseline (speedup 1.0000x reference)
#include <cuda_runtime.h>
#include <cstdint>

#define BATCH 131072
#define BT    64          // threads (batches) per block, producers only
#define NL    24
#define PH    6           // links per phase -> 384 B output per batch-phase
#define NPHASE (NL / PH)  // 4
#define ROWF4 25          // float4 per smem row: 24 data + 1 pad (400 B stride)

__device__ __forceinline__ void bulk_store384(void* gdst, uint32_t ssrc) {
    asm volatile(
        "cp.async.bulk.global.shared::cta.bulk_group [%0], [%1], 384;"
        :: "l"(gdst), "r"(ssrc) : "memory");
}

__global__ __launch_bounds__(BT)
void fk_kernel(const float* __restrict__ q,
               const float* __restrict__ axes,
               const float* __restrict__ t_fix,
               float* __restrict__ out) {
    __shared__ float s_ax[NL][3];
    __shared__ float s_tf[NL][3];
    __shared__ __align__(16) float4 stage[2][BT * ROWF4];   // 2 x 25600 B

    int tid = threadIdx.x;
    if (tid < NL) {
        float ax = axes[tid * 3 + 0];
        float ay = axes[tid * 3 + 1];
        float az = axes[tid * 3 + 2];
        float inv = rsqrtf(ax * ax + ay * ay + az * az);
        s_ax[tid][0] = ax * inv;
        s_ax[tid][1] = ay * inv;
        s_ax[tid][2] = az * inv;
        s_tf[tid][0] = t_fix[tid * 3 + 0];
        s_tf[tid][1] = t_fix[tid * 3 + 1];
        s_tf[tid][2] = t_fix[tid * 3 + 2];
    }
    __syncthreads();

    int b = blockIdx.x * BT + tid;

    // Private 400-B-strided rows; nothing cross-thread in the stage buffers.
    float4* row0 = &stage[0][tid * ROWF4];
    float4* row1 = &stage[1][tid * ROWF4];

    // Pre-fill constant bottom rows (slots 3,7,11,15,19,23) once per buffer.
    const float4 BOT = make_float4(0.f, 0.f, 0.f, 1.f);
    #pragma unroll
    for (int l = 0; l < PH; l++) {
        row0[l * 4 + 3] = BOT;
        row1[l * 4 + 3] = BOT;
    }

    const uint32_t srow0 = (uint32_t)__cvta_generic_to_shared(row0);
    const uint32_t srow1 = (uint32_t)__cvta_generic_to_shared(row1);

    char* gdst = (char*)out + (size_t)b * (NL * 64);   // 1536 B per batch

    // Load all 24 joint angles upfront (6x LDG.128, coalesced).
    float qv[NL];
    {
        const float4* qr = reinterpret_cast<const float4*>(q + (size_t)b * NL);
        #pragma unroll
        for (int i = 0; i < NL / 4; i++) {
            float4 v = qr[i];
            qv[i * 4 + 0] = v.x;
            qv[i * 4 + 1] = v.y;
            qv[i * 4 + 2] = v.z;
            qv[i * 4 + 3] = v.w;
        }
    }

    // Running pose (registers)
    float R00 = 1.f, R01 = 0.f, R02 = 0.f;
    float R10 = 0.f, R11 = 1.f, R12 = 0.f;
    float R20 = 0.f, R21 = 0.f, R22 = 1.f;
    float t0 = 0.f, t1 = 0.f, t2 = 0.f;

    #pragma unroll
    for (int p = 0; p < NPHASE; p++) {
        // Buffer reuse guard: retire the copy issued at phase p-2.
        if (p >= 2) asm volatile("cp.async.bulk.wait_group 1;" ::: "memory");

        float4* r = (p & 1) ? row1 : row0;

        #pragma unroll
        for (int ll = 0; ll < PH; ll++) {
            int l = p * PH + ll;
            float s, c;
            __sincosf(qv[l], &s, &c);
            float C = 1.f - c;

            float ax = s_ax[l][0], ay = s_ax[l][1], az = s_ax[l][2];

            // Rodrigues: Rj = c*I + s*K + (1-c)*(a a^T)
            float j00 = fmaf(C * ax, ax, c);
            float j01 = fmaf(C * ax, ay, -s * az);
            float j02 = fmaf(C * ax, az,  s * ay);
            float j10 = fmaf(C * ay, ax,  s * az);
            float j11 = fmaf(C * ay, ay, c);
            float j12 = fmaf(C * ay, az, -s * ax);
            float j20 = fmaf(C * az, ax, -s * ay);
            float j21 = fmaf(C * az, ay,  s * ax);
            float j22 = fmaf(C * az, az, c);

            // t += R @ tf (parent R)
            float tf0 = s_tf[l][0], tf1 = s_tf[l][1], tf2 = s_tf[l][2];
            t0 = fmaf(R00, tf0, fmaf(R01, tf1, fmaf(R02, tf2, t0)));
            t1 = fmaf(R10, tf0, fmaf(R11, tf1, fmaf(R12, tf2, t1)));
            t2 = fmaf(R20, tf0, fmaf(R21, tf1, fmaf(R22, tf2, t2)));

            // R = R @ Rj
            float n00 = fmaf(R00, j00, fmaf(R01, j10, R02 * j20));
            float n01 = fmaf(R00, j01, fmaf(R01, j11, R02 * j21));
            float n02 = fmaf(R00, j02, fmaf(R01, j12, R02 * j22));
            float n10 = fmaf(R10, j00, fmaf(R11, j10, R12 * j20));
            float n11 = fmaf(R10, j01, fmaf(R11, j11, R12 * j21));
            float n12 = fmaf(R10, j02, fmaf(R11, j12, R12 * j22));
            float n20 = fmaf(R20, j00, fmaf(R21, j10, R22 * j20));
            float n21 = fmaf(R20, j01, fmaf(R21, j11, R22 * j21));
            float n22 = fmaf(R20, j02, fmaf(R21, j12, R22 * j22));
            R00 = n00; R01 = n01; R02 = n02;
            R10 = n10; R11 = n11; R12 = n12;
            R20 = n20; R21 = n21; R22 = n22;

            // Stage 3 pose rows; slot 4*ll+3 holds the pre-filled bottom row.
            r[ll * 4 + 0] = make_float4(R00, R01, R02, t0);
            r[ll * 4 + 1] = make_float4(R10, R11, R12, t1);
            r[ll * 4 + 2] = make_float4(R20, R21, R22, t2);
        }

        // Order this thread's STS before the async-proxy bulk read.
        asm volatile("fence.proxy.async.shared::cta;" ::: "memory");
        bulk_store384(gdst + p * 384, (p & 1) ? srow1 : srow0);
        asm volatile("cp.async.bulk.commit_group;" ::: "memory");
    }

    // All of this thread's copies must complete before exit.
    asm volatile("cp.async.bulk.wait_group 0;" ::: "memory");
}

extern "C" void kernel_launch(void* const* d_in, const int* in_sizes, int n_in,
                              void* d_out, int out_size) {
    const float* q     = (const float*)d_in[0];
    // d_in[1] = qd, unused by the reference computation
    const float* axes  = (const float*)d_in[2];
    const float* t_fix = (const float*)d_in[3];
    float* out = (float*)d_out;

    dim3 block(BT);
    dim3 grid(BATCH / BT);
    fk_kernel<<<grid, block>>>(q, axes, t_fix, out);
}

// round 13
// speedup vs baseline: 1.1113x; 1.1113x over previous
#include <cuda_runtime.h>
#include <cstdint>

#define BATCH 131072
#define BT    64          // producer threads (batches) per block
#define NWR   128         // writer threads
#define NTHR  (BT + NWR)  // 192
#define NL    24
#define PH    4           // links per phase
#define NPHASE (NL / PH)  // 6
#define NBUF  3           // ring depth
#define STRIDE 13         // float4 slots per batch per buffer (12 data + 1 pad)

#define BAR_SYNC(id)   asm volatile("bar.sync %0, %1;"   :: "r"(id), "r"(NTHR) : "memory")
#define BAR_ARRIVE(id) asm volatile("bar.arrive %0, %1;" :: "r"(id), "r"(NTHR) : "memory")
// barrier ids: 1+buf = data-ready(buf), 4+buf = buffer-free(buf), buf = p % 3

__global__ __launch_bounds__(NTHR, 5)
void fk_kernel(const float* __restrict__ q,
               const float* __restrict__ axes,
               const float* __restrict__ t_fix,
               float* __restrict__ out) {
    __shared__ float  s_ax[NL][3];
    __shared__ float  s_tf[NL][3];
    __shared__ __align__(16) float4 stage[NBUF][BT * STRIDE];   // 3 x 13312 B

    int tid = threadIdx.x;
    if (tid < NL) {
        float ax = axes[tid * 3 + 0];
        float ay = axes[tid * 3 + 1];
        float az = axes[tid * 3 + 2];
        float inv = rsqrtf(ax * ax + ay * ay + az * az);
        s_ax[tid][0] = ax * inv;
        s_ax[tid][1] = ay * inv;
        s_ax[tid][2] = az * inv;
        s_tf[tid][0] = t_fix[tid * 3 + 0];
        s_tf[tid][1] = t_fix[tid * 3 + 1];
        s_tf[tid][2] = t_fix[tid * 3 + 2];
    }
    __syncthreads();

    if (tid < BT) {
        // ================= PRODUCER: compute chain, stage to smem =========
        int b = blockIdx.x * BT + tid;
        const float4* qr = reinterpret_cast<const float4*>(q + (size_t)b * NL);

        float R00 = 1.f, R01 = 0.f, R02 = 0.f;
        float R10 = 0.f, R11 = 1.f, R12 = 0.f;
        float R20 = 0.f, R21 = 0.f, R22 = 1.f;
        float t0 = 0.f, t1 = 0.f, t2 = 0.f;

        float4 qnext = qr[0];

        #pragma unroll
        for (int p = 0; p < NPHASE; p++) {
            int bufi = p % NBUF;
            if (p >= NBUF) BAR_SYNC(4 + bufi);   // buffer consumed (phase p-3)

            float4 qc = qnext;
            if (p < NPHASE - 1) qnext = qr[p + 1];
            float qv[PH] = {qc.x, qc.y, qc.z, qc.w};

            float4* buf = stage[bufi];

            #pragma unroll
            for (int ll = 0; ll < PH; ll++) {
                int l = p * PH + ll;
                float s, c;
                __sincosf(qv[ll], &s, &c);
                float C = 1.f - c;

                float ax = s_ax[l][0], ay = s_ax[l][1], az = s_ax[l][2];

                // Rodrigues: Rj = c*I + s*K + (1-c)*(a a^T)
                float j00 = fmaf(C * ax, ax, c);
                float j01 = fmaf(C * ax, ay, -s * az);
                float j02 = fmaf(C * ax, az,  s * ay);
                float j10 = fmaf(C * ay, ax,  s * az);
                float j11 = fmaf(C * ay, ay, c);
                float j12 = fmaf(C * ay, az, -s * ax);
                float j20 = fmaf(C * az, ax, -s * ay);
                float j21 = fmaf(C * az, ay,  s * ax);
                float j22 = fmaf(C * az, az, c);

                // t += R @ tf (parent R)
                float tf0 = s_tf[l][0], tf1 = s_tf[l][1], tf2 = s_tf[l][2];
                t0 = fmaf(R00, tf0, fmaf(R01, tf1, fmaf(R02, tf2, t0)));
                t1 = fmaf(R10, tf0, fmaf(R11, tf1, fmaf(R12, tf2, t1)));
                t2 = fmaf(R20, tf0, fmaf(R21, tf1, fmaf(R22, tf2, t2)));

                // R = R @ Rj
                float n00 = fmaf(R00, j00, fmaf(R01, j10, R02 * j20));
                float n01 = fmaf(R00, j01, fmaf(R01, j11, R02 * j21));
                float n02 = fmaf(R00, j02, fmaf(R01, j12, R02 * j22));
                float n10 = fmaf(R10, j00, fmaf(R11, j10, R12 * j20));
                float n11 = fmaf(R10, j01, fmaf(R11, j11, R12 * j21));
                float n12 = fmaf(R10, j02, fmaf(R11, j12, R12 * j22));
                float n20 = fmaf(R20, j00, fmaf(R21, j10, R22 * j20));
                float n21 = fmaf(R20, j01, fmaf(R21, j11, R22 * j21));
                float n22 = fmaf(R20, j02, fmaf(R21, j12, R22 * j22));
                R00 = n00; R01 = n01; R02 = n02;
                R10 = n10; R11 = n11; R12 = n12;
                R20 = n20; R21 = n21; R22 = n22;

                int sbase = tid * STRIDE + ll * 3;
                buf[sbase + 0] = make_float4(R00, R01, R02, t0);
                buf[sbase + 1] = make_float4(R10, R11, R12, t1);
                buf[sbase + 2] = make_float4(R20, R21, R22, t2);
            }
            BAR_ARRIVE(1 + bufi);                // data for phase p ready
        }
    } else {
        // ================= WRITER: coalesced global stores =================
        int w = tid - BT;                        // 0..127
        const int  j     = w & 15;               // float4 index within phase region
        const int  bl0   = w >> 4;               // first batch serviced (0..7)
        const bool isbot = (j & 3) == 3;
        const int  slot  = (j >> 2) * 3 + (j & 3);
        const float4 BOT = make_float4(0.f, 0.f, 0.f, 1.f);

        // L2-residency split: ~44% of blocks (88 MB) use default (evict-normal)
        // stores so their lines stay in L2 and are overwritten in-place on the
        // next graph replay; the rest stream with evict-first.
        const bool resident = (blockIdx.x % 16u) < 7u;

        float4* gout = reinterpret_cast<float4*>(out);
        const long gbase = (long)blockIdx.x * BT * 96;   // 96 float4 per batch

        #pragma unroll
        for (int p = 0; p < NPHASE; p++) {
            int bufi = p % NBUF;
            BAR_SYNC(1 + bufi);                  // wait data for phase p
            const float4* buf = stage[bufi];

            // Gather first (8 independent LDS), then store (8 STG).
            float4 v[8];
            #pragma unroll
            for (int k = 0; k < 8; k++) {
                int bl = bl0 + k * 8;
                v[k] = isbot ? BOT : buf[bl * STRIDE + slot];
            }
            if (resident) {
                #pragma unroll
                for (int k = 0; k < 8; k++) {
                    int bl = bl0 + k * 8;
                    gout[gbase + (long)bl * 96 + p * 16 + j] = v[k];
                }
            } else {
                #pragma unroll
                for (int k = 0; k < 8; k++) {
                    int bl = bl0 + k * 8;
                    __stcs(&gout[gbase + (long)bl * 96 + p * 16 + j], v[k]);
                }
            }
            // Producers only wait for buffers of phases p' = p+3 <= NPHASE-1.
            if (p < NPHASE - NBUF) BAR_ARRIVE(4 + bufi);
        }
    }
}

extern "C" void kernel_launch(void* const* d_in, const int* in_sizes, int n_in,
                              void* d_out, int out_size) {
    const float* q     = (const float*)d_in[0];
    // d_in[1] = qd, unused by the reference computation
    const float* axes  = (const float*)d_in[2];
    const float* t_fix = (const float*)d_in[3];
    float* out = (float*)d_out;

    dim3 block(NTHR);
    dim3 grid(BATCH / BT);
    fk_kernel<<<grid, block>>>(q, axes, t_fix, out);
}

// round 14
// speedup vs baseline: 1.2493x; 1.1242x over previous
#include <cuda_runtime.h>
#include <cstdint>

#define BATCH 131072
#define NL    24
#define NTHR  256                      // 64 batches per block, 4 threads/batch
#define NBLK  ((BATCH * 4) / NTHR)     // 2048

__global__ __launch_bounds__(NTHR)
void fk_kernel(const float* __restrict__ q,
               const float* __restrict__ axes,
               const float* __restrict__ t_fix,
               float* __restrict__ out) {
    __shared__ float s_ax[NL][3];
    __shared__ float s_tf[NL][3];

    int tid = threadIdx.x;
    if (tid < NL) {
        float ax = axes[tid * 3 + 0];
        float ay = axes[tid * 3 + 1];
        float az = axes[tid * 3 + 2];
        float inv = rsqrtf(ax * ax + ay * ay + az * az);
        s_ax[tid][0] = ax * inv;
        s_ax[tid][1] = ay * inv;
        s_ax[tid][2] = az * inv;
        s_tf[tid][0] = t_fix[tid * 3 + 0];
        s_tf[tid][1] = t_fix[tid * 3 + 1];
        s_tf[tid][2] = t_fix[tid * 3 + 2];
    }
    __syncthreads();

    int gtid  = blockIdx.x * NTHR + tid;
    int batch = gtid >> 2;             // 4 consecutive lanes share a batch
    int row   = gtid & 3;              // output row this thread owns

    const float4* qr = reinterpret_cast<const float4*>(q + (size_t)batch * NL);

    // This thread's row of the running pose. Row 3 starts (0,0,0,1) and the
    // uniform update keeps it constant: Ra=Rb=Rc=0 -> rotation update yields 0,
    // T = fma(0,..., T) stays 1. No divergence anywhere.
    float Ra = (row == 0) ? 1.f : 0.f;
    float Rb = (row == 1) ? 1.f : 0.f;
    float Rc = (row == 2) ? 1.f : 0.f;
    float T  = (row == 3) ? 1.f : 0.f;

    float4* gout = reinterpret_cast<float4*>(out) + (size_t)batch * (NL * 4) + row;

    float4 qnext = qr[0];

    #pragma unroll
    for (int g = 0; g < NL / 4; g++) {
        float4 qc = qnext;
        if (g < NL / 4 - 1) qnext = qr[g + 1];
        float qv[4] = {qc.x, qc.y, qc.z, qc.w};

        #pragma unroll
        for (int ll = 0; ll < 4; ll++) {
            int l = g * 4 + ll;
            float s, c;
            __sincosf(qv[ll], &s, &c);
            float C = 1.f - c;

            float ax = s_ax[l][0], ay = s_ax[l][1], az = s_ax[l][2];

            // Rodrigues: Rj = c*I + s*K + (1-c)*(a a^T)
            float j00 = fmaf(C * ax, ax, c);
            float j01 = fmaf(C * ax, ay, -s * az);
            float j02 = fmaf(C * ax, az,  s * ay);
            float j10 = fmaf(C * ay, ax,  s * az);
            float j11 = fmaf(C * ay, ay, c);
            float j12 = fmaf(C * ay, az, -s * ax);
            float j20 = fmaf(C * az, ax, -s * ay);
            float j21 = fmaf(C * az, ay,  s * ax);
            float j22 = fmaf(C * az, az, c);

            // t[row] += R[row,:] . tf   (parent R)
            float tf0 = s_tf[l][0], tf1 = s_tf[l][1], tf2 = s_tf[l][2];
            T = fmaf(Ra, tf0, fmaf(Rb, tf1, fmaf(Rc, tf2, T)));

            // R[row,:] = R[row,:] @ Rj
            float na = fmaf(Ra, j00, fmaf(Rb, j10, Rc * j20));
            float nb = fmaf(Ra, j01, fmaf(Rb, j11, Rc * j21));
            float nc = fmaf(Ra, j02, fmaf(Rb, j12, Rc * j22));
            Ra = na; Rb = nb; Rc = nc;

            // Direct store of this row of pose l. Lanes 4k..4k+3 write 64 B
            // contiguous; a warp-op covers 8 such groups (16 sectors / 512 B).
            __stcs(&gout[l * 4], make_float4(Ra, Rb, Rc, T));
        }
    }
}

extern "C" void kernel_launch(void* const* d_in, const int* in_sizes, int n_in,
                              void* d_out, int out_size) {
    const float* q     = (const float*)d_in[0];
    // d_in[1] = qd, unused by the reference computation
    const float* axes  = (const float*)d_in[2];
    const float* t_fix = (const float*)d_in[3];
    float* out = (float*)d_out;

    dim3 block(NTHR);
    dim3 grid(NBLK);
    fk_kernel<<<grid, block>>>(q, axes, t_fix, out);
}